// round 15
// baseline (speedup 1.0000x reference)
#include <cuda_runtime.h>
#include <cuda_bf16.h>
#include <math.h>

// Problem dims (fixed by setup_inputs)
#define BB 64
#define KK 8
#define FF 24
#define DD 32   // KK + FF
#define HH 64
#define LL 2048
#define CC 64
#define XAUG_ELEMS (BB * LL * CC)   // 8388608

// Per-batch selected transform + its intensity (scratch; no allocation allowed)
__device__ int   g_sel_k[BB];
__device__ float g_sel_t[BB];

// ---------------------------------------------------------------------------
// Kernel 1: per-batch dual MLP, split-K across 256 threads, with ALL weight
// loads register-prefetched at kernel entry (addresses are input-independent,
// so every layer's weight-load latency overlaps in one issue burst).
//   layers 1-2: 2 threads per neuron (both MLPs side by side), shared combine
//   layer 3:    16 threads per neuron, shfl-tree reduce
// Publishes g_sel and fires the PDL trigger BEFORE writing tail outputs.
// (Proven in R12 — unchanged.)
// ---------------------------------------------------------------------------
__global__ void __launch_bounds__(256) setup_kernel(
    const float* __restrict__ prev_prob,   // (B,K)
    const float* __restrict__ features,    // (B,F)
    const float* __restrict__ gumbel,      // (B,K)
    const float* __restrict__ pW1, const float* __restrict__ pb1,
    const float* __restrict__ pW2, const float* __restrict__ pb2,
    const float* __restrict__ pW3, const float* __restrict__ pb3,
    const float* __restrict__ iW1, const float* __restrict__ ib1,
    const float* __restrict__ iW2, const float* __restrict__ ib2,
    const float* __restrict__ iW3, const float* __restrict__ ib3,
    float* __restrict__ out_prob,          // (B,K)
    float* __restrict__ out_int,           // (B,K)
    float* __restrict__ out_sel)           // (B,)
{
    const int b   = blockIdx.x;
    const int tid = threadIdx.x;           // 0..255

    const int  neu  = tid & 127;           // neuron across both MLPs (0..127)
    const int  half = tid >> 7;            // 0/1: which K-split half
    const int  lt   = neu & 63;            // neuron within its MLP
    const bool isP  = (neu < 64);          // prob MLP vs intensity MLP
    const int  mlp  = isP ? 0 : 1;

    // layer-3 role (independent decomposition of the same 256 threads)
    const int  neu3  = tid >> 4;           // 0..15
    const int  part3 = tid & 15;           // 0..15
    const bool isP3  = (neu3 < 8);
    const int  k3    = neu3 & 7;

    __shared__ float s_in[DD];
    __shared__ float s_gum[KK];
    __shared__ float part[256];
    __shared__ float h1[2][HH];
    __shared__ float h2[2][HH];
    __shared__ float s_logit[KK];
    __shared__ float s_int[KK];

    // ======== FRONT-ISSUE EVERYTHING (input + all weight slices) ========
    if (tid < KK)            s_in[tid] = prev_prob[b * KK + tid];
    else if (tid < DD)       s_in[tid] = features[b * FF + (tid - KK)];
    else if (tid < DD + KK)  s_gum[tid - DD] = gumbel[b * KK + (tid - DD)];

    float w1r[16];
    {
        const float* W1 = isP ? pW1 : iW1;
        const int i0 = half * 16;
        #pragma unroll
        for (int i = 0; i < 16; i++) w1r[i] = W1[(i0 + i) * HH + lt];
    }
    float w2r[32];
    {
        const float* W2 = isP ? pW2 : iW2;
        const int i0 = half * 32;
        #pragma unroll
        for (int i = 0; i < 32; i++) w2r[i] = W2[(i0 + i) * HH + lt];
    }
    float w3r[4];
    {
        const float* W3 = isP3 ? pW3 : iW3;
        const int i0 = part3 * 4;
        #pragma unroll
        for (int i = 0; i < 4; i++) w3r[i] = W3[(i0 + i) * KK + k3];
    }
    const float b1v = (tid < 128) ? (isP ? pb1 : ib1)[lt] : 0.f;
    const float b2v = (tid < 128) ? (isP ? pb2 : ib2)[lt] : 0.f;
    const float b3v = (part3 == 0) ? (isP3 ? pb3 : ib3)[k3] : 0.f;
    __syncthreads();

    // ======== layer 1: 32 inputs, split 16+16 ========
    {
        const int i0 = half * 16;
        float a = 0.f;
        #pragma unroll
        for (int i = 0; i < 16; i++) a = fmaf(s_in[i0 + i], w1r[i], a);
        part[tid] = a;
    }
    __syncthreads();
    if (tid < 128)
        h1[mlp][lt] = fmaxf(part[tid] + part[tid + 128] + b1v, 0.f);
    __syncthreads();

    // ======== layer 2: 64 inputs, split 32+32 ========
    {
        const float* h  = h1[mlp];
        const int i0 = half * 32;
        float a = 0.f;
        #pragma unroll
        for (int i = 0; i < 32; i++) a = fmaf(h[i0 + i], w2r[i], a);
        part[tid] = a;
    }
    __syncthreads();
    if (tid < 128)
        h2[mlp][lt] = fmaxf(part[tid] + part[tid + 128] + b2v, 0.f);
    __syncthreads();

    // ======== layer 3: 16 neurons x 16 threads, shfl-tree reduce ========
    {
        const unsigned grp_mask = 0xffffu << (((tid & 31) >> 4) << 4);
        const float* h = h2[isP3 ? 0 : 1];
        const int i0 = part3 * 4;
        float a = 0.f;
        #pragma unroll
        for (int i = 0; i < 4; i++) a = fmaf(h[i0 + i], w3r[i], a);
        a += __shfl_down_sync(grp_mask, a, 8, 16);
        a += __shfl_down_sync(grp_mask, a, 4, 16);
        a += __shfl_down_sync(grp_mask, a, 2, 16);
        a += __shfl_down_sync(grp_mask, a, 1, 16);
        if (part3 == 0) {
            a += b3v;
            if (isP3) s_logit[k3] = a;
            else      s_int[k3]   = (a > 20.f) ? a : log1pf(expf(a)); // softplus
        }
    }
    __syncthreads();

    if (tid == 0) {
        // argmax(logits + gumbel) == argmax(y_soft); selection is exactly
        // one-hot (y_hard + y_soft - stop_grad(y_soft) == y_hard numerically).
        int best = 0;
        float bv = s_logit[0] + s_gum[0];
        #pragma unroll
        for (int k = 1; k < KK; k++) {
            float v = s_logit[k] + s_gum[k];
            if (v > bv) { bv = v; best = k; }
        }
        g_sel_k[b] = best;
        g_sel_t[b] = s_int[best];
        out_sel[b] = (float)best;
    }
    __syncthreads();
#if __CUDA_ARCH__ >= 900
    // Release the dependent apply kernel ASAP — it only needs g_sel_*.
    cudaTriggerProgrammaticLaunchCompletion();
#endif

    // ---- tail outputs (after trigger; off everyone's critical path) ----
    if (tid == 0) {
        float m = s_logit[0];
        #pragma unroll
        for (int k = 1; k < KK; k++) m = fmaxf(m, s_logit[k]);
        float e[KK]; float sum = 0.f;
        #pragma unroll
        for (int k = 0; k < KK; k++) { e[k] = expf(s_logit[k] - m); sum += e[k]; }
        float inv = 1.f / sum;
        #pragma unroll
        for (int k = 0; k < KK; k++) out_prob[b * KK + k] = e[k] * inv;
        #pragma unroll
        for (int k = 0; k < KK; k++) out_int[b * KK + k] = s_int[k];
    }
}

// ---------------------------------------------------------------------------
// Kernel 2: apply the single selected transform per batch.
// 512-thread blocks, grid (32, B) = 2048 CTAs (half of R12's 4096 -> half the
// per-CTA fixed costs), 2 float4/thread, plain stores. Addressing via shifts
// (batch offset = b << 15 float4s). Loads are k-independent (k==7 flip applied
// on the store side) and issued before the PDL wait.
// ---------------------------------------------------------------------------
__global__ void __launch_bounds__(512) apply_kernel(
    const float* __restrict__ x, float* __restrict__ out)
{
    const int b = blockIdx.y;

    const float4* __restrict__ xi = (const float4*)x   + ((size_t)b << 15);
    float4*       __restrict__ oo = (float4*)      out + ((size_t)b << 15);

    const int base = (blockIdx.x << 10) + threadIdx.x;  // 32 blocks * 1024 = 32768

    // k-independent loads, issued before the dependency wait
    float4 v0 = xi[base];
    float4 v1 = xi[base + 512];

#if __CUDA_ARCH__ >= 900
    cudaGridDependencySynchronize();   // wait for setup; makes g_sel visible
#endif
    const int   k = g_sel_k[b];
    const float t = g_sel_t[b];

    if (k == 7) {
        // time reversal: identity values, flipped (still coalesced) store position
        int i0 = base, i1 = base + 512;
        oo[((LL - 1 - (i0 >> 4)) << 4) + (i0 & 15)] = v0;
        oo[((LL - 1 - (i1 >> 4)) << 4) + (i1 & 15)] = v1;
    } else if (k == 4) {
        const float A = 1.f + t;
        v0.x = tanhf(v0.x * A); v0.y = tanhf(v0.y * A);
        v0.z = tanhf(v0.z * A); v0.w = tanhf(v0.w * A);
        v1.x = tanhf(v1.x * A); v1.y = tanhf(v1.y * A);
        v1.z = tanhf(v1.z * A); v1.w = tanhf(v1.w * A);
        oo[base] = v0; oo[base + 512] = v1;
    } else if (k == 6) {
        v0.x = fmaf(t, sinf(v0.x), v0.x); v0.y = fmaf(t, sinf(v0.y), v0.y);
        v0.z = fmaf(t, sinf(v0.z), v0.z); v0.w = fmaf(t, sinf(v0.w), v0.w);
        v1.x = fmaf(t, sinf(v1.x), v1.x); v1.y = fmaf(t, sinf(v1.y), v1.y);
        v1.z = fmaf(t, sinf(v1.z), v1.z); v1.w = fmaf(t, sinf(v1.w), v1.w);
        oo[base] = v0; oo[base + 512] = v1;
    } else {
        // k in {0,1,2,3,5}: affine A*x + Bc
        float A = 1.f, Bc = 0.f;
        if      (k == 1) A = 1.f + t;
        else if (k == 2) Bc = t;
        else if (k == 3) A = 1.f - t;
        else if (k == 5) A = expf(-t);
        v0.x = fmaf(v0.x, A, Bc); v0.y = fmaf(v0.y, A, Bc);
        v0.z = fmaf(v0.z, A, Bc); v0.w = fmaf(v0.w, A, Bc);
        v1.x = fmaf(v1.x, A, Bc); v1.y = fmaf(v1.y, A, Bc);
        v1.z = fmaf(v1.z, A, Bc); v1.w = fmaf(v1.w, A, Bc);
        oo[base] = v0; oo[base + 512] = v1;
    }
}

extern "C" void kernel_launch(void* const* d_in, const int* in_sizes, int n_in,
                              void* d_out, int out_size)
{
    const float* x         = (const float*)d_in[0];
    const float* prev_prob = (const float*)d_in[1];
    const float* features  = (const float*)d_in[2];
    const float* gumbel    = (const float*)d_in[3];
    // d_in[4] = log_temperature: dead for forward values (exact one-hot selection;
    // tau>0 never changes the argmax; prob uses the raw softmax of logits).
    const float* pW1 = (const float*)d_in[5];
    const float* pb1 = (const float*)d_in[6];
    const float* pW2 = (const float*)d_in[7];
    const float* pb2 = (const float*)d_in[8];
    const float* pW3 = (const float*)d_in[9];
    const float* pb3 = (const float*)d_in[10];
    const float* iW1 = (const float*)d_in[11];
    const float* ib1 = (const float*)d_in[12];
    const float* iW2 = (const float*)d_in[13];
    const float* ib2 = (const float*)d_in[14];
    const float* iW3 = (const float*)d_in[15];
    const float* ib3 = (const float*)d_in[16];

    float* out      = (float*)d_out;
    float* out_prob = out + XAUG_ELEMS;              // (B,K)
    float* out_int  = out_prob + BB * KK;            // (B,K)
    float* out_sel  = out_int  + BB * KK;            // (B,)

    setup_kernel<<<BB, 256>>>(prev_prob, features, gumbel,
                              pW1, pb1, pW2, pb2, pW3, pb3,
                              iW1, ib1, iW2, ib2, iW3, ib3,
                              out_prob, out_int, out_sel);

    // Apply kernel with Programmatic Dependent Launch: begins (and issues
    // its x loads) while setup drains; synchronizes before reading g_sel.
    cudaLaunchConfig_t cfg = {};
    cfg.gridDim  = dim3(32, BB, 1);
    cfg.blockDim = dim3(512, 1, 1);
    cfg.dynamicSmemBytes = 0;
    cfg.stream = 0;
    cudaLaunchAttribute attr[1];
    attr[0].id = cudaLaunchAttributeProgrammaticStreamSerialization;
    attr[0].val.programmaticStreamSerializationAllowed = 1;
    cfg.attrs = attr;
    cfg.numAttrs = 1;
    cudaLaunchKernelEx(&cfg, apply_kernel, x, out);
}